// round 15
// baseline (speedup 1.0000x reference)
#include <cuda_runtime.h>
#include <cuda_bf16.h>
#include <math.h>
#include <stdint.h>

#define NN    50000
#define EE    800000
#define FIN   256
#define ETOT  (EE + NN)
#define NEG_SLOPE 0.2f

// ---------------- scratch (device globals) ----------------------------------
__device__ __nv_bfloat16 g_h1[NN * 256];   // layer-1 linear output, bf16 [N,4,64]
__device__ float g_as1[NN * 4];
__device__ float g_ad1[NN * 4];
__device__ float g_h2[NN * 32];            // layer-2 linear output
__device__ float g_as2[NN];
__device__ float g_ad2[NN];
// split-bf16 operands for tensor-core GEMMs
__device__ __nv_bfloat16 g_w1hi[256 * 256];   // [n][k] (transposed W1)
__device__ __nv_bfloat16 g_w1lo[256 * 256];
__device__ __nv_bfloat16 g_a2hi[NN * 256];    // relu(agg1+b1) split
__device__ __nv_bfloat16 g_a2lo[NN * 256];
__device__ __nv_bfloat16 g_w2hi[32 * 256];    // [n][k] (transposed W2)
__device__ __nv_bfloat16 g_w2lo[32 * 256];
// CSR (dst-bucketed incoming edges; slot stores src node id)
__device__ int   g_deg[NN];
__device__ int   g_rowstart[NN + 1];
__device__ int   g_col[ETOT];

// ---------------- CSR build --------------------------------------------------
__global__ void k_deg_init(int n) {
    int i = blockIdx.x * blockDim.x + threadIdx.x;
    if (i < n) g_deg[i] = 1;
}
__global__ void k_count(const int* __restrict__ ei, int E) {
    int e = blockIdx.x * blockDim.x + threadIdx.x;
    if (e < E) atomicAdd(&g_deg[ei[E + e]], 1);
}
__global__ void k_scan(int n) {
    __shared__ int sh[1024];
    int tid = threadIdx.x;
    int chunk = (n + 1023) / 1024;
    int beg = tid * chunk;
    int end = min(beg + chunk, n);
    int s = 0;
    for (int i = beg; i < end; i++) s += g_deg[i];
    sh[tid] = s;
    __syncthreads();
    #pragma unroll
    for (int off = 1; off < 1024; off <<= 1) {
        int v = (tid >= off) ? sh[tid - off] : 0;
        __syncthreads();
        sh[tid] += v;
        __syncthreads();
    }
    int run = (tid == 0) ? 0 : sh[tid - 1];
    for (int i = beg; i < end; i++) {
        int c = g_deg[i];
        g_rowstart[i] = run;
        g_deg[i] = run;
        run += c;
    }
    if (tid == 0) g_rowstart[n] = sh[1023];
}
__global__ void k_scatter(const int* __restrict__ ei, int E, int etot) {
    int e = blockIdx.x * blockDim.x + threadIdx.x;
    if (e >= etot) return;
    int s, d;
    if (e < E) { s = ei[e]; d = ei[E + e]; }
    else       { s = d = e - E; }
    int pos = atomicAdd(&g_deg[d], 1);
    g_col[pos] = s;
}

// ---------------- split-bf16 weight prep (W1 + W2 in one kernel) ------------
__global__ void k_prep_w(const float* __restrict__ W1, const float* __restrict__ W2) {
    int i = blockIdx.x * blockDim.x + threadIdx.x;
    if (i < 256 * 256) {
        int n = i >> 8, k = i & 255;
        float f = W1[k * 256 + n];
        __nv_bfloat16 hi = __float2bfloat16_rn(f);
        g_w1hi[i] = hi;
        g_w1lo[i] = __float2bfloat16_rn(f - __bfloat162float(hi));
    } else if (i < 256 * 256 + 32 * 256) {
        int j = i - 256 * 256;
        int n = j >> 8, k = j & 255;
        float f = W2[k * 32 + n];
        __nv_bfloat16 hi = __float2bfloat16_rn(f);
        g_w2hi[j] = hi;
        g_w2lo[j] = __float2bfloat16_rn(f - __bfloat162float(hi));
    }
}

// ---------------- mma.sync helper -------------------------------------------
#define PAD_K 40          // 32 + 8 bf16 padding -> 80-byte rows (16B aligned)
__device__ __forceinline__ void mma16816(float* c, const uint32_t* a, const uint32_t* b) {
    asm volatile(
        "mma.sync.aligned.m16n8k16.row.col.f32.bf16.bf16.f32 "
        "{%0,%1,%2,%3}, {%4,%5,%6,%7}, {%8,%9}, {%0,%1,%2,%3};"
        : "+f"(c[0]), "+f"(c[1]), "+f"(c[2]), "+f"(c[3])
        : "r"(a[0]), "r"(a[1]), "r"(a[2]), "r"(a[3]), "r"(b[0]), "r"(b[1]));
}

// ------- GEMM1 via mma.sync bf16 (split hi/lo) + fused attn1 dots -----------
__global__ void __launch_bounds__(256) k_gemm1_mma(const float* __restrict__ x,
                                                   const float* __restrict__ att_src,
                                                   const float* __restrict__ att_dst, int M) {
    __shared__ __nv_bfloat16 sAhi[128 * PAD_K];
    __shared__ __nv_bfloat16 sAlo[128 * PAD_K];
    __shared__ __nv_bfloat16 sBhi[128 * PAD_K];
    __shared__ __nv_bfloat16 sBlo[128 * PAD_K];

    int tid = threadIdx.x;
    int wid = tid >> 5, lane = tid & 31;
    int wm = wid >> 1, wn = wid & 1;          // 4 x 2 warps
    int row0 = blockIdx.y * 128;
    int col0 = blockIdx.x * 128;

    float acc[2][8][4] = {};

    int lq = lane & 3;
    int lr = lane >> 2;

    for (int kc = 0; kc < 256; kc += 32) {
        #pragma unroll
        for (int i = 0; i < 2; i++) {
            int slot = tid + i * 256;
            int r = slot >> 2, q = slot & 3;
            int gr = row0 + r;
            __nv_bfloat16 hbuf[8], lbuf[8];
            if (gr < M) {
                const float* px = x + (size_t)gr * 256 + kc + q * 8;
                float4 f0 = *(const float4*)px;
                float4 f1 = *(const float4*)(px + 4);
                float fv[8] = {f0.x, f0.y, f0.z, f0.w, f1.x, f1.y, f1.z, f1.w};
                #pragma unroll
                for (int t = 0; t < 8; t++) {
                    __nv_bfloat16 hi = __float2bfloat16_rn(fv[t]);
                    hbuf[t] = hi;
                    lbuf[t] = __float2bfloat16_rn(fv[t] - __bfloat162float(hi));
                }
            } else {
                #pragma unroll
                for (int t = 0; t < 8; t++) { hbuf[t] = __float2bfloat16_rn(0.f); lbuf[t] = hbuf[t]; }
            }
            *(uint4*)(sAhi + r * PAD_K + q * 8) = *(uint4*)hbuf;
            *(uint4*)(sAlo + r * PAD_K + q * 8) = *(uint4*)lbuf;
        }
        #pragma unroll
        for (int i = 0; i < 2; i++) {
            int slot = tid + i * 256;
            int r = slot >> 2, q = slot & 3;
            int gn = col0 + r;
            *(uint4*)(sBhi + r * PAD_K + q * 8) = *(const uint4*)(g_w1hi + (size_t)gn * 256 + kc + q * 8);
            *(uint4*)(sBlo + r * PAD_K + q * 8) = *(const uint4*)(g_w1lo + (size_t)gn * 256 + kc + q * 8);
        }
        __syncthreads();

        #pragma unroll
        for (int ks = 0; ks < 2; ks++) {
            int kb = ks * 16;
            uint32_t ahi[2][4], alo[2][4], bhi[8][2], blo[8][2];
            #pragma unroll
            for (int mt = 0; mt < 2; mt++) {
                int rbase = wm * 32 + mt * 16;
                const __nv_bfloat16* p0h = sAhi + (rbase + lr) * PAD_K + kb + lq * 2;
                const __nv_bfloat16* p1h = sAhi + (rbase + 8 + lr) * PAD_K + kb + lq * 2;
                const __nv_bfloat16* p0l = sAlo + (rbase + lr) * PAD_K + kb + lq * 2;
                const __nv_bfloat16* p1l = sAlo + (rbase + 8 + lr) * PAD_K + kb + lq * 2;
                ahi[mt][0] = *(const uint32_t*)p0h;
                ahi[mt][1] = *(const uint32_t*)p1h;
                ahi[mt][2] = *(const uint32_t*)(p0h + 8);
                ahi[mt][3] = *(const uint32_t*)(p1h + 8);
                alo[mt][0] = *(const uint32_t*)p0l;
                alo[mt][1] = *(const uint32_t*)p1l;
                alo[mt][2] = *(const uint32_t*)(p0l + 8);
                alo[mt][3] = *(const uint32_t*)(p1l + 8);
            }
            #pragma unroll
            for (int nt = 0; nt < 8; nt++) {
                int nbase = wn * 64 + nt * 8;
                const __nv_bfloat16* ph = sBhi + (nbase + lr) * PAD_K + kb + lq * 2;
                const __nv_bfloat16* pl = sBlo + (nbase + lr) * PAD_K + kb + lq * 2;
                bhi[nt][0] = *(const uint32_t*)ph;
                bhi[nt][1] = *(const uint32_t*)(ph + 8);
                blo[nt][0] = *(const uint32_t*)pl;
                blo[nt][1] = *(const uint32_t*)(pl + 8);
            }
            #pragma unroll
            for (int mt = 0; mt < 2; mt++)
                #pragma unroll
                for (int nt = 0; nt < 8; nt++) {
                    mma16816(acc[mt][nt], ahi[mt], bhi[nt]);
                    mma16816(acc[mt][nt], ahi[mt], blo[nt]);
                    mma16816(acc[mt][nt], alo[mt], bhi[nt]);
                }
        }
        __syncthreads();
    }

    int h = (col0 >> 6) + wn;   // this warp's head
    #pragma unroll
    for (int mt = 0; mt < 2; mt++) {
        int r0 = row0 + wm * 32 + mt * 16 + lr;
        float ps0 = 0.f, pd0 = 0.f, ps1 = 0.f, pd1 = 0.f;
        #pragma unroll
        for (int nt = 0; nt < 8; nt++) {
            int c = col0 + wn * 64 + nt * 8 + lq * 2;
            int ci = h * 64 + nt * 8 + lq * 2;
            float a0 = __ldg(&att_src[ci]), a1 = __ldg(&att_src[ci + 1]);
            float d0 = __ldg(&att_dst[ci]), d1 = __ldg(&att_dst[ci + 1]);
            ps0 += acc[mt][nt][0] * a0 + acc[mt][nt][1] * a1;
            pd0 += acc[mt][nt][0] * d0 + acc[mt][nt][1] * d1;
            ps1 += acc[mt][nt][2] * a0 + acc[mt][nt][3] * a1;
            pd1 += acc[mt][nt][2] * d0 + acc[mt][nt][3] * d1;
            if (r0 < M)
                *(__nv_bfloat162*)(g_h1 + (size_t)r0 * 256 + c) =
                    __float22bfloat162_rn(make_float2(acc[mt][nt][0], acc[mt][nt][1]));
            if (r0 + 8 < M)
                *(__nv_bfloat162*)(g_h1 + (size_t)(r0 + 8) * 256 + c) =
                    __float22bfloat162_rn(make_float2(acc[mt][nt][2], acc[mt][nt][3]));
        }
        #pragma unroll
        for (int off = 1; off <= 2; off <<= 1) {
            ps0 += __shfl_xor_sync(0xffffffffu, ps0, off);
            pd0 += __shfl_xor_sync(0xffffffffu, pd0, off);
            ps1 += __shfl_xor_sync(0xffffffffu, ps1, off);
            pd1 += __shfl_xor_sync(0xffffffffu, pd1, off);
        }
        if (lq == 0) {
            if (r0 < M)     { g_as1[r0 * 4 + h] = ps0;       g_ad1[r0 * 4 + h] = pd0; }
            if (r0 + 8 < M) { g_as1[(r0 + 8) * 4 + h] = ps1; g_ad1[(r0 + 8) * 4 + h] = pd1; }
        }
    }
}

// -- fused layer-1 softmax + aggregate + bias + relu -> split bf16 -----------
// block = 128 threads = 4 warps; warp h owns head h's alpha computation
// (lane-parallel over edges, computed ONCE into smem), all threads aggregate.
// Channel-pair tid has head tid>>5 == warp id.
__global__ void __launch_bounds__(128) k_agg1(const float* __restrict__ b1) {
    __shared__ float s_alpha[64][4];
    __shared__ int   s_col[64];
    __shared__ float s_rsum[4];

    int d = blockIdx.x;
    int tid = threadIdx.x;
    int wid = tid >> 5;                 // == head
    int lane = tid & 31;
    int beg = g_rowstart[d], end = g_rowstart[d + 1];
    float adv = __ldg(&g_ad1[d * 4 + wid]);

    // phase A: lane-parallel max for this warp's head
    float mx = -3.4e38f;
    for (int i = beg + lane; i < end; i += 32) {
        float v = __ldg(&g_as1[__ldg(&g_col[i]) * 4 + wid]) + adv;
        v = (v > 0.f) ? v : NEG_SLOPE * v;
        mx = fmaxf(mx, v);
    }
    #pragma unroll
    for (int off = 16; off >= 1; off >>= 1)
        mx = fmaxf(mx, __shfl_xor_sync(0xffffffffu, mx, off));

    // phase B: 64-edge chunks; alphas to smem (once per head), then aggregate
    float sum = 0.f;
    float acc0 = 0.f, acc1 = 0.f;
    for (int base = beg; base < end; base += 64) {
        int cnt = min(64, end - base);
        for (int t = lane; t < cnt; t += 32) {
            int c = __ldg(&g_col[base + t]);
            if (wid == 0) s_col[t] = c;
            float v = __ldg(&g_as1[c * 4 + wid]) + adv;
            v = (v > 0.f) ? v : NEG_SLOPE * v;
            float ex = __expf(v - mx);
            s_alpha[t][wid] = ex;
            sum += ex;
        }
        __syncthreads();
        for (int j = 0; j < cnt; j++) {
            int s = s_col[j];
            float al = s_alpha[j][wid];
            float2 v = __bfloat1622float2(*(const __nv_bfloat162*)(g_h1 + (size_t)s * 256 + tid * 2));
            acc0 += v.x * al;
            acc1 += v.y * al;
        }
        __syncthreads();
    }
    // per-head sum reduce + share
    #pragma unroll
    for (int off = 16; off >= 1; off >>= 1)
        sum += __shfl_xor_sync(0xffffffffu, sum, off);
    if (lane == 0) s_rsum[wid] = 1.f / (sum + 1e-16f);
    __syncthreads();

    float rs = s_rsum[wid];
    float val0 = fmaxf(acc0 * rs + b1[tid * 2], 0.f);
    float val1 = fmaxf(acc1 * rs + b1[tid * 2 + 1], 0.f);
    __nv_bfloat16 hi0 = __float2bfloat16_rn(val0);
    __nv_bfloat16 hi1 = __float2bfloat16_rn(val1);
    __nv_bfloat162 hp; hp.x = hi0; hp.y = hi1;
    __nv_bfloat162 lp;
    lp.x = __float2bfloat16_rn(val0 - __bfloat162float(hi0));
    lp.y = __float2bfloat16_rn(val1 - __bfloat162float(hi1));
    *(__nv_bfloat162*)(g_a2hi + (size_t)d * 256 + tid * 2) = hp;
    *(__nv_bfloat162*)(g_a2lo + (size_t)d * 256 + tid * 2) = lp;
}

// ------- GEMM2 via mma.sync bf16 (split hi/lo) + fused attn2 dots -----------
__global__ void __launch_bounds__(256) k_gemm2_mma(const float* __restrict__ att_src,
                                                   const float* __restrict__ att_dst, int M) {
    __shared__ __nv_bfloat16 sAhi[128 * PAD_K];
    __shared__ __nv_bfloat16 sAlo[128 * PAD_K];
    __shared__ __nv_bfloat16 sBhi[32 * PAD_K];
    __shared__ __nv_bfloat16 sBlo[32 * PAD_K];

    int tid = threadIdx.x;
    int wid = tid >> 5, lane = tid & 31;
    int row0 = blockIdx.x * 128;
    int lq = lane & 3;
    int lr = lane >> 2;

    float acc[4][4] = {};

    for (int kc = 0; kc < 256; kc += 32) {
        #pragma unroll
        for (int i = 0; i < 2; i++) {
            int slot = tid + i * 256;
            int r = slot >> 2, q = slot & 3;
            int gr = row0 + r;
            uint4 vh = make_uint4(0, 0, 0, 0), vl = make_uint4(0, 0, 0, 0);
            if (gr < M) {
                vh = *(const uint4*)(g_a2hi + (size_t)gr * 256 + kc + q * 8);
                vl = *(const uint4*)(g_a2lo + (size_t)gr * 256 + kc + q * 8);
            }
            *(uint4*)(sAhi + r * PAD_K + q * 8) = vh;
            *(uint4*)(sAlo + r * PAD_K + q * 8) = vl;
        }
        if (tid < 128) {
            int r = tid >> 2, q = tid & 3;
            *(uint4*)(sBhi + r * PAD_K + q * 8) = *(const uint4*)(g_w2hi + (size_t)r * 256 + kc + q * 8);
            *(uint4*)(sBlo + r * PAD_K + q * 8) = *(const uint4*)(g_w2lo + (size_t)r * 256 + kc + q * 8);
        }
        __syncthreads();

        #pragma unroll
        for (int ks = 0; ks < 2; ks++) {
            int kb = ks * 16;
            uint32_t ahi[4], alo[4], bhi[4][2], blo[4][2];
            int rbase = wid * 16;
            const __nv_bfloat16* p0h = sAhi + (rbase + lr) * PAD_K + kb + lq * 2;
            const __nv_bfloat16* p1h = sAhi + (rbase + 8 + lr) * PAD_K + kb + lq * 2;
            const __nv_bfloat16* p0l = sAlo + (rbase + lr) * PAD_K + kb + lq * 2;
            const __nv_bfloat16* p1l = sAlo + (rbase + 8 + lr) * PAD_K + kb + lq * 2;
            ahi[0] = *(const uint32_t*)p0h;
            ahi[1] = *(const uint32_t*)p1h;
            ahi[2] = *(const uint32_t*)(p0h + 8);
            ahi[3] = *(const uint32_t*)(p1h + 8);
            alo[0] = *(const uint32_t*)p0l;
            alo[1] = *(const uint32_t*)p1l;
            alo[2] = *(const uint32_t*)(p0l + 8);
            alo[3] = *(const uint32_t*)(p1l + 8);
            #pragma unroll
            for (int nt = 0; nt < 4; nt++) {
                int nbase = nt * 8;
                const __nv_bfloat16* ph = sBhi + (nbase + lr) * PAD_K + kb + lq * 2;
                const __nv_bfloat16* pl = sBlo + (nbase + lr) * PAD_K + kb + lq * 2;
                bhi[nt][0] = *(const uint32_t*)ph;
                bhi[nt][1] = *(const uint32_t*)(ph + 8);
                blo[nt][0] = *(const uint32_t*)pl;
                blo[nt][1] = *(const uint32_t*)(pl + 8);
            }
            #pragma unroll
            for (int nt = 0; nt < 4; nt++) {
                mma16816(acc[nt], ahi, bhi[nt]);
                mma16816(acc[nt], ahi, blo[nt]);
                mma16816(acc[nt], alo, bhi[nt]);
            }
        }
        __syncthreads();
    }

    int r0 = row0 + wid * 16 + lr;
    float ps0 = 0.f, pd0 = 0.f, ps1 = 0.f, pd1 = 0.f;
    #pragma unroll
    for (int nt = 0; nt < 4; nt++) {
        int c = nt * 8 + lq * 2;
        float a0 = __ldg(&att_src[c]), a1 = __ldg(&att_src[c + 1]);
        float d0 = __ldg(&att_dst[c]), d1 = __ldg(&att_dst[c + 1]);
        ps0 += acc[nt][0] * a0 + acc[nt][1] * a1;
        pd0 += acc[nt][0] * d0 + acc[nt][1] * d1;
        ps1 += acc[nt][2] * a0 + acc[nt][3] * a1;
        pd1 += acc[nt][2] * d0 + acc[nt][3] * d1;
        if (r0 < M)
            *(float2*)(g_h2 + (size_t)r0 * 32 + c) = make_float2(acc[nt][0], acc[nt][1]);
        if (r0 + 8 < M)
            *(float2*)(g_h2 + (size_t)(r0 + 8) * 32 + c) = make_float2(acc[nt][2], acc[nt][3]);
    }
    #pragma unroll
    for (int off = 1; off <= 2; off <<= 1) {
        ps0 += __shfl_xor_sync(0xffffffffu, ps0, off);
        pd0 += __shfl_xor_sync(0xffffffffu, pd0, off);
        ps1 += __shfl_xor_sync(0xffffffffu, ps1, off);
        pd1 += __shfl_xor_sync(0xffffffffu, pd1, off);
    }
    if (lq == 0) {
        if (r0 < M)     { g_as2[r0] = ps0;     g_ad2[r0] = pd0; }
        if (r0 + 8 < M) { g_as2[r0 + 8] = ps1; g_ad2[r0 + 8] = pd1; }
    }
}

// -- fused layer-2 softmax+aggregate+bias+log_softmax (warp/dst, lane-par) ---
__global__ void __launch_bounds__(256) k_agg2(const float* __restrict__ b2,
                                              float* __restrict__ out, int n) {
    int d = (blockIdx.x * blockDim.x + threadIdx.x) >> 5;
    int lane = threadIdx.x & 31;
    if (d >= n) return;
    int beg = g_rowstart[d], end = g_rowstart[d + 1];
    float adv = __ldg(&g_ad2[d]);

    float mx = -3.4e38f;
    for (int i = beg + lane; i < end; i += 32) {
        float v = __ldg(&g_as2[__ldg(&g_col[i])]) + adv;
        v = (v > 0.f) ? v : NEG_SLOPE * v;
        mx = fmaxf(mx, v);
    }
    #pragma unroll
    for (int off = 16; off >= 1; off >>= 1)
        mx = fmaxf(mx, __shfl_xor_sync(0xffffffffu, mx, off));

    float sum = 0.f, acc = 0.f;
    for (int base = beg; base < end; base += 32) {
        int i = base + lane;
        float myal = 0.f; int mycol = 0;
        if (i < end) {
            mycol = __ldg(&g_col[i]);
            float v = __ldg(&g_as2[mycol]) + adv;
            v = (v > 0.f) ? v : NEG_SLOPE * v;
            myal = __expf(v - mx);
        }
        sum += myal;
        int cnt = min(32, end - base);
        for (int j = 0; j < cnt; j++) {
            float al = __shfl_sync(0xffffffffu, myal, j);
            int s    = __shfl_sync(0xffffffffu, mycol, j);
            acc += __ldg(&g_h2[(size_t)s * 32 + lane]) * al;
        }
    }
    #pragma unroll
    for (int off = 16; off >= 1; off >>= 1)
        sum += __shfl_xor_sync(0xffffffffu, sum, off);

    float val = acc * (1.f / (sum + 1e-16f)) + b2[lane];
    float m2 = val;
    #pragma unroll
    for (int off = 16; off >= 1; off >>= 1)
        m2 = fmaxf(m2, __shfl_xor_sync(0xffffffffu, m2, off));
    float ex = __expf(val - m2);
    float s2 = ex;
    #pragma unroll
    for (int off = 16; off >= 1; off >>= 1)
        s2 += __shfl_xor_sync(0xffffffffu, s2, off);
    out[(size_t)d * 32 + lane] = val - m2 - logf(s2);
}

// ---------------- launch -----------------------------------------------------
extern "C" void kernel_launch(void* const* d_in, const int* in_sizes, int n_in,
                              void* d_out, int out_size) {
    const float* x    = (const float*)d_in[0];
    const int*   ei   = (const int*)d_in[1];
    const float* W1   = (const float*)d_in[2];
    const float* as1  = (const float*)d_in[3];
    const float* ad1  = (const float*)d_in[4];
    const float* b1   = (const float*)d_in[5];
    const float* W2   = (const float*)d_in[6];
    const float* as2  = (const float*)d_in[7];
    const float* ad2  = (const float*)d_in[8];
    const float* b2   = (const float*)d_in[9];
    float* out = (float*)d_out;

    int n = in_sizes[0] / FIN;
    int E = in_sizes[1] / 2;
    int etot = E + n;

    static cudaStream_t s2 = nullptr;
    static cudaEvent_t evFork = nullptr, evJoin = nullptr;
    if (!s2) {
        cudaStreamCreateWithFlags(&s2, cudaStreamNonBlocking);
        cudaEventCreateWithFlags(&evFork, cudaEventDisableTiming);
        cudaEventCreateWithFlags(&evJoin, cudaEventDisableTiming);
    }

    // fork: CSR build on side stream, overlapped with prep + GEMM1
    cudaEventRecord(evFork, 0);
    cudaStreamWaitEvent(s2, evFork, 0);
    k_deg_init<<<(n + 255) / 256, 256, 0, s2>>>(n);
    k_count<<<(E + 255) / 256, 256, 0, s2>>>(ei, E);
    k_scan<<<1, 1024, 0, s2>>>(n);
    k_scatter<<<(etot + 255) / 256, 256, 0, s2>>>(ei, E, etot);
    cudaEventRecord(evJoin, s2);

    // main stream: dense path
    k_prep_w<<<(256 * 256 + 32 * 256 + 255) / 256, 256>>>(W1, W2);

    dim3 g1(2, (n + 127) / 128);
    k_gemm1_mma<<<g1, 256>>>(x, as1, ad1, n);

    // join: aggregation needs the CSR
    cudaStreamWaitEvent(0, evJoin, 0);

    k_agg1<<<n, 128>>>(b1);

    k_gemm2_mma<<<(n + 127) / 128, 256>>>(as2, ad2, n);
    k_agg2<<<(n * 32 + 255) / 256, 256>>>(b2, out, n);
}

// round 16
// speedup vs baseline: 1.1773x; 1.1773x over previous
#include <cuda_runtime.h>
#include <cuda_bf16.h>
#include <math.h>
#include <stdint.h>

#define NN    50000
#define EE    800000
#define FIN   256
#define ETOT  (EE + NN)
#define NEG_SLOPE 0.2f

// ---------------- scratch (device globals) ----------------------------------
__device__ __nv_bfloat16 g_h1[NN * 256];   // layer-1 linear output, bf16 [N,4,64]
__device__ float g_as1[NN * 4];
__device__ float g_ad1[NN * 4];
__device__ float g_h2[NN * 32];            // layer-2 linear output
__device__ float g_as2[NN];
__device__ float g_ad2[NN];
// bf16 operands for tensor-core GEMMs
__device__ __nv_bfloat16 g_w1hi[256 * 256];   // [n][k] (transposed W1), bf16
__device__ __nv_bfloat16 g_a2[NN * 256];      // relu(agg1+b1), bf16
__device__ __nv_bfloat16 g_w2hi[32 * 256];    // [n][k] (transposed W2) split
__device__ __nv_bfloat16 g_w2lo[32 * 256];
// CSR (dst-bucketed incoming edges; slot stores src node id)
__device__ int   g_deg[NN];
__device__ int   g_rowstart[NN + 1];
__device__ int   g_col[ETOT];

// ---------------- CSR build --------------------------------------------------
__global__ void k_deg_init(int n) {
    int i = blockIdx.x * blockDim.x + threadIdx.x;
    if (i < n) g_deg[i] = 1;
}
__global__ void k_count(const int* __restrict__ ei, int E) {
    int e = blockIdx.x * blockDim.x + threadIdx.x;
    if (e < E) atomicAdd(&g_deg[ei[E + e]], 1);
}
__global__ void k_scan(int n) {
    __shared__ int sh[1024];
    int tid = threadIdx.x;
    int chunk = (n + 1023) / 1024;
    int beg = tid * chunk;
    int end = min(beg + chunk, n);
    int s = 0;
    for (int i = beg; i < end; i++) s += g_deg[i];
    sh[tid] = s;
    __syncthreads();
    #pragma unroll
    for (int off = 1; off < 1024; off <<= 1) {
        int v = (tid >= off) ? sh[tid - off] : 0;
        __syncthreads();
        sh[tid] += v;
        __syncthreads();
    }
    int run = (tid == 0) ? 0 : sh[tid - 1];
    for (int i = beg; i < end; i++) {
        int c = g_deg[i];
        g_rowstart[i] = run;
        g_deg[i] = run;
        run += c;
    }
    if (tid == 0) g_rowstart[n] = sh[1023];
}
__global__ void k_scatter(const int* __restrict__ ei, int E, int etot) {
    int e = blockIdx.x * blockDim.x + threadIdx.x;
    if (e >= etot) return;
    int s, d;
    if (e < E) { s = ei[e]; d = ei[E + e]; }
    else       { s = d = e - E; }
    int pos = atomicAdd(&g_deg[d], 1);
    g_col[pos] = s;
}

// ---------------- weight prep: W1 bf16, W2 split bf16 ------------------------
__global__ void k_prep_w(const float* __restrict__ W1, const float* __restrict__ W2) {
    int i = blockIdx.x * blockDim.x + threadIdx.x;
    if (i < 256 * 256) {
        int n = i >> 8, k = i & 255;
        g_w1hi[i] = __float2bfloat16_rn(W1[k * 256 + n]);
    } else if (i < 256 * 256 + 32 * 256) {
        int j = i - 256 * 256;
        int n = j >> 8, k = j & 255;
        float f = W2[k * 32 + n];
        __nv_bfloat16 hi = __float2bfloat16_rn(f);
        g_w2hi[j] = hi;
        g_w2lo[j] = __float2bfloat16_rn(f - __bfloat162float(hi));
    }
}

// ---------------- mma.sync helper -------------------------------------------
#define PAD_K 40          // 32 + 8 bf16 padding -> 80-byte rows (16B aligned)
__device__ __forceinline__ void mma16816(float* c, const uint32_t* a, const uint32_t* b) {
    asm volatile(
        "mma.sync.aligned.m16n8k16.row.col.f32.bf16.bf16.f32 "
        "{%0,%1,%2,%3}, {%4,%5,%6,%7}, {%8,%9}, {%0,%1,%2,%3};"
        : "+f"(c[0]), "+f"(c[1]), "+f"(c[2]), "+f"(c[3])
        : "r"(a[0]), "r"(a[1]), "r"(a[2]), "r"(a[3]), "r"(b[0]), "r"(b[1]));
}

// ------- GEMM1 pure bf16 mma.sync + fused attn1 dots ------------------------
// CTA tile 128x128, K chunks of 32; 8 warps (4 M x 2 N), warp tile 32x64.
// h1 stored bf16 anyway -> split products add nothing; 1 MMA per tile.
__global__ void __launch_bounds__(256) k_gemm1_mma(const float* __restrict__ x,
                                                   const float* __restrict__ att_src,
                                                   const float* __restrict__ att_dst, int M) {
    __shared__ __nv_bfloat16 sA[128 * PAD_K];
    __shared__ __nv_bfloat16 sB[128 * PAD_K];

    int tid = threadIdx.x;
    int wid = tid >> 5, lane = tid & 31;
    int wm = wid >> 1, wn = wid & 1;          // 4 x 2 warps
    int row0 = blockIdx.y * 128;
    int col0 = blockIdx.x * 128;

    float acc[2][8][4] = {};

    int lq = lane & 3;
    int lr = lane >> 2;

    for (int kc = 0; kc < 256; kc += 32) {
        // A fill: fp32 x -> bf16
        #pragma unroll
        for (int i = 0; i < 2; i++) {
            int slot = tid + i * 256;
            int r = slot >> 2, q = slot & 3;
            int gr = row0 + r;
            __nv_bfloat16 hbuf[8];
            if (gr < M) {
                const float* px = x + (size_t)gr * 256 + kc + q * 8;
                float4 f0 = *(const float4*)px;
                float4 f1 = *(const float4*)(px + 4);
                hbuf[0] = __float2bfloat16_rn(f0.x);
                hbuf[1] = __float2bfloat16_rn(f0.y);
                hbuf[2] = __float2bfloat16_rn(f0.z);
                hbuf[3] = __float2bfloat16_rn(f0.w);
                hbuf[4] = __float2bfloat16_rn(f1.x);
                hbuf[5] = __float2bfloat16_rn(f1.y);
                hbuf[6] = __float2bfloat16_rn(f1.z);
                hbuf[7] = __float2bfloat16_rn(f1.w);
            } else {
                #pragma unroll
                for (int t = 0; t < 8; t++) hbuf[t] = __float2bfloat16_rn(0.f);
            }
            *(uint4*)(sA + r * PAD_K + q * 8) = *(uint4*)hbuf;
        }
        #pragma unroll
        for (int i = 0; i < 2; i++) {
            int slot = tid + i * 256;
            int r = slot >> 2, q = slot & 3;
            int gn = col0 + r;
            *(uint4*)(sB + r * PAD_K + q * 8) = *(const uint4*)(g_w1hi + (size_t)gn * 256 + kc + q * 8);
        }
        __syncthreads();

        #pragma unroll
        for (int ks = 0; ks < 2; ks++) {
            int kb = ks * 16;
            uint32_t a[2][4], b[8][2];
            #pragma unroll
            for (int mt = 0; mt < 2; mt++) {
                int rbase = wm * 32 + mt * 16;
                const __nv_bfloat16* p0 = sA + (rbase + lr) * PAD_K + kb + lq * 2;
                const __nv_bfloat16* p1 = sA + (rbase + 8 + lr) * PAD_K + kb + lq * 2;
                a[mt][0] = *(const uint32_t*)p0;
                a[mt][1] = *(const uint32_t*)p1;
                a[mt][2] = *(const uint32_t*)(p0 + 8);
                a[mt][3] = *(const uint32_t*)(p1 + 8);
            }
            #pragma unroll
            for (int nt = 0; nt < 8; nt++) {
                int nbase = wn * 64 + nt * 8;
                const __nv_bfloat16* p = sB + (nbase + lr) * PAD_K + kb + lq * 2;
                b[nt][0] = *(const uint32_t*)p;
                b[nt][1] = *(const uint32_t*)(p + 8);
            }
            #pragma unroll
            for (int mt = 0; mt < 2; mt++)
                #pragma unroll
                for (int nt = 0; nt < 8; nt++)
                    mma16816(acc[mt][nt], a[mt], b[nt]);
        }
        __syncthreads();
    }

    int h = (col0 >> 6) + wn;   // this warp's head
    #pragma unroll
    for (int mt = 0; mt < 2; mt++) {
        int r0 = row0 + wm * 32 + mt * 16 + lr;
        float ps0 = 0.f, pd0 = 0.f, ps1 = 0.f, pd1 = 0.f;
        #pragma unroll
        for (int nt = 0; nt < 8; nt++) {
            int c = col0 + wn * 64 + nt * 8 + lq * 2;
            int ci = h * 64 + nt * 8 + lq * 2;
            float a0 = __ldg(&att_src[ci]), a1 = __ldg(&att_src[ci + 1]);
            float d0 = __ldg(&att_dst[ci]), d1 = __ldg(&att_dst[ci + 1]);
            ps0 += acc[mt][nt][0] * a0 + acc[mt][nt][1] * a1;
            pd0 += acc[mt][nt][0] * d0 + acc[mt][nt][1] * d1;
            ps1 += acc[mt][nt][2] * a0 + acc[mt][nt][3] * a1;
            pd1 += acc[mt][nt][2] * d0 + acc[mt][nt][3] * d1;
            if (r0 < M)
                *(__nv_bfloat162*)(g_h1 + (size_t)r0 * 256 + c) =
                    __float22bfloat162_rn(make_float2(acc[mt][nt][0], acc[mt][nt][1]));
            if (r0 + 8 < M)
                *(__nv_bfloat162*)(g_h1 + (size_t)(r0 + 8) * 256 + c) =
                    __float22bfloat162_rn(make_float2(acc[mt][nt][2], acc[mt][nt][3]));
        }
        #pragma unroll
        for (int off = 1; off <= 2; off <<= 1) {
            ps0 += __shfl_xor_sync(0xffffffffu, ps0, off);
            pd0 += __shfl_xor_sync(0xffffffffu, pd0, off);
            ps1 += __shfl_xor_sync(0xffffffffu, ps1, off);
            pd1 += __shfl_xor_sync(0xffffffffu, pd1, off);
        }
        if (lq == 0) {
            if (r0 < M)     { g_as1[r0 * 4 + h] = ps0;       g_ad1[r0 * 4 + h] = pd0; }
            if (r0 + 8 < M) { g_as1[(r0 + 8) * 4 + h] = ps1; g_ad1[(r0 + 8) * 4 + h] = pd1; }
        }
    }
}

// -- fused layer-1 softmax + aggregate + bias + relu -> bf16 ------------------
// block = 128 threads = 4 warps; warp h owns head h's alpha computation
// (lane-parallel, computed ONCE into smem), all threads aggregate.
__global__ void __launch_bounds__(128) k_agg1(const float* __restrict__ b1) {
    __shared__ float s_alpha[64][4];
    __shared__ int   s_col[64];
    __shared__ float s_rsum[4];

    int d = blockIdx.x;
    int tid = threadIdx.x;
    int wid = tid >> 5;                 // == head
    int lane = tid & 31;
    int beg = g_rowstart[d], end = g_rowstart[d + 1];
    float adv = __ldg(&g_ad1[d * 4 + wid]);

    float mx = -3.4e38f;
    for (int i = beg + lane; i < end; i += 32) {
        float v = __ldg(&g_as1[__ldg(&g_col[i]) * 4 + wid]) + adv;
        v = (v > 0.f) ? v : NEG_SLOPE * v;
        mx = fmaxf(mx, v);
    }
    #pragma unroll
    for (int off = 16; off >= 1; off >>= 1)
        mx = fmaxf(mx, __shfl_xor_sync(0xffffffffu, mx, off));

    float sum = 0.f;
    float acc0 = 0.f, acc1 = 0.f;
    for (int base = beg; base < end; base += 64) {
        int cnt = min(64, end - base);
        for (int t = lane; t < cnt; t += 32) {
            int c = __ldg(&g_col[base + t]);
            if (wid == 0) s_col[t] = c;
            float v = __ldg(&g_as1[c * 4 + wid]) + adv;
            v = (v > 0.f) ? v : NEG_SLOPE * v;
            float ex = __expf(v - mx);
            s_alpha[t][wid] = ex;
            sum += ex;
        }
        __syncthreads();
        for (int j = 0; j < cnt; j++) {
            int s = s_col[j];
            float al = s_alpha[j][wid];
            float2 v = __bfloat1622float2(*(const __nv_bfloat162*)(g_h1 + (size_t)s * 256 + tid * 2));
            acc0 += v.x * al;
            acc1 += v.y * al;
        }
        __syncthreads();
    }
    #pragma unroll
    for (int off = 16; off >= 1; off >>= 1)
        sum += __shfl_xor_sync(0xffffffffu, sum, off);
    if (lane == 0) s_rsum[wid] = 1.f / (sum + 1e-16f);
    __syncthreads();

    float rs = s_rsum[wid];
    float val0 = fmaxf(acc0 * rs + b1[tid * 2], 0.f);
    float val1 = fmaxf(acc1 * rs + b1[tid * 2 + 1], 0.f);
    *(__nv_bfloat162*)(g_a2 + (size_t)d * 256 + tid * 2) =
        __float22bfloat162_rn(make_float2(val0, val1));
}

// ------- GEMM2: a2(bf16) x W2(split) , 2 products + fused attn2 dots --------
// CTA tile 128x32, 8 warps (8 M x 1 N), warp tile 16x32; K chunks of 32.
__global__ void __launch_bounds__(256) k_gemm2_mma(const float* __restrict__ att_src,
                                                   const float* __restrict__ att_dst, int M) {
    __shared__ __nv_bfloat16 sA[128 * PAD_K];
    __shared__ __nv_bfloat16 sBhi[32 * PAD_K];
    __shared__ __nv_bfloat16 sBlo[32 * PAD_K];

    int tid = threadIdx.x;
    int wid = tid >> 5, lane = tid & 31;
    int row0 = blockIdx.x * 128;
    int lq = lane & 3;
    int lr = lane >> 2;

    float acc[4][4] = {};

    for (int kc = 0; kc < 256; kc += 32) {
        #pragma unroll
        for (int i = 0; i < 2; i++) {
            int slot = tid + i * 256;
            int r = slot >> 2, q = slot & 3;
            int gr = row0 + r;
            uint4 v = make_uint4(0, 0, 0, 0);
            if (gr < M) v = *(const uint4*)(g_a2 + (size_t)gr * 256 + kc + q * 8);
            *(uint4*)(sA + r * PAD_K + q * 8) = v;
        }
        if (tid < 128) {
            int r = tid >> 2, q = tid & 3;
            *(uint4*)(sBhi + r * PAD_K + q * 8) = *(const uint4*)(g_w2hi + (size_t)r * 256 + kc + q * 8);
            *(uint4*)(sBlo + r * PAD_K + q * 8) = *(const uint4*)(g_w2lo + (size_t)r * 256 + kc + q * 8);
        }
        __syncthreads();

        #pragma unroll
        for (int ks = 0; ks < 2; ks++) {
            int kb = ks * 16;
            uint32_t a[4], bhi[4][2], blo[4][2];
            int rbase = wid * 16;
            const __nv_bfloat16* p0 = sA + (rbase + lr) * PAD_K + kb + lq * 2;
            const __nv_bfloat16* p1 = sA + (rbase + 8 + lr) * PAD_K + kb + lq * 2;
            a[0] = *(const uint32_t*)p0;
            a[1] = *(const uint32_t*)p1;
            a[2] = *(const uint32_t*)(p0 + 8);
            a[3] = *(const uint32_t*)(p1 + 8);
            #pragma unroll
            for (int nt = 0; nt < 4; nt++) {
                int nbase = nt * 8;
                const __nv_bfloat16* ph = sBhi + (nbase + lr) * PAD_K + kb + lq * 2;
                const __nv_bfloat16* pl = sBlo + (nbase + lr) * PAD_K + kb + lq * 2;
                bhi[nt][0] = *(const uint32_t*)ph;
                bhi[nt][1] = *(const uint32_t*)(ph + 8);
                blo[nt][0] = *(const uint32_t*)pl;
                blo[nt][1] = *(const uint32_t*)(pl + 8);
            }
            #pragma unroll
            for (int nt = 0; nt < 4; nt++) {
                mma16816(acc[nt], a, bhi[nt]);
                mma16816(acc[nt], a, blo[nt]);
            }
        }
        __syncthreads();
    }

    int r0 = row0 + wid * 16 + lr;
    float ps0 = 0.f, pd0 = 0.f, ps1 = 0.f, pd1 = 0.f;
    #pragma unroll
    for (int nt = 0; nt < 4; nt++) {
        int c = nt * 8 + lq * 2;
        float a0 = __ldg(&att_src[c]), a1 = __ldg(&att_src[c + 1]);
        float d0 = __ldg(&att_dst[c]), d1 = __ldg(&att_dst[c + 1]);
        ps0 += acc[nt][0] * a0 + acc[nt][1] * a1;
        pd0 += acc[nt][0] * d0 + acc[nt][1] * d1;
        ps1 += acc[nt][2] * a0 + acc[nt][3] * a1;
        pd1 += acc[nt][2] * d0 + acc[nt][3] * d1;
        if (r0 < M)
            *(float2*)(g_h2 + (size_t)r0 * 32 + c) = make_float2(acc[nt][0], acc[nt][1]);
        if (r0 + 8 < M)
            *(float2*)(g_h2 + (size_t)(r0 + 8) * 32 + c) = make_float2(acc[nt][2], acc[nt][3]);
    }
    #pragma unroll
    for (int off = 1; off <= 2; off <<= 1) {
        ps0 += __shfl_xor_sync(0xffffffffu, ps0, off);
        pd0 += __shfl_xor_sync(0xffffffffu, pd0, off);
        ps1 += __shfl_xor_sync(0xffffffffu, ps1, off);
        pd1 += __shfl_xor_sync(0xffffffffu, pd1, off);
    }
    if (lq == 0) {
        if (r0 < M)     { g_as2[r0] = ps0;     g_ad2[r0] = pd0; }
        if (r0 + 8 < M) { g_as2[r0 + 8] = ps1; g_ad2[r0 + 8] = pd1; }
    }
}

// -- fused layer-2 softmax+aggregate+bias+log_softmax (warp/dst, lane-par) ---
__global__ void __launch_bounds__(256) k_agg2(const float* __restrict__ b2,
                                              float* __restrict__ out, int n) {
    int d = (blockIdx.x * blockDim.x + threadIdx.x) >> 5;
    int lane = threadIdx.x & 31;
    if (d >= n) return;
    int beg = g_rowstart[d], end = g_rowstart[d + 1];
    float adv = __ldg(&g_ad2[d]);

    float mx = -3.4e38f;
    for (int i = beg + lane; i < end; i += 32) {
        float v = __ldg(&g_as2[__ldg(&g_col[i])]) + adv;
        v = (v > 0.f) ? v : NEG_SLOPE * v;
        mx = fmaxf(mx, v);
    }
    #pragma unroll
    for (int off = 16; off >= 1; off >>= 1)
        mx = fmaxf(mx, __shfl_xor_sync(0xffffffffu, mx, off));

    float sum = 0.f, acc = 0.f;
    for (int base = beg; base < end; base += 32) {
        int i = base + lane;
        float myal = 0.f; int mycol = 0;
        if (i < end) {
            mycol = __ldg(&g_col[i]);
            float v = __ldg(&g_as2[mycol]) + adv;
            v = (v > 0.f) ? v : NEG_SLOPE * v;
            myal = __expf(v - mx);
        }
        sum += myal;
        int cnt = min(32, end - base);
        for (int j = 0; j < cnt; j++) {
            float al = __shfl_sync(0xffffffffu, myal, j);
            int s    = __shfl_sync(0xffffffffu, mycol, j);
            acc += __ldg(&g_h2[(size_t)s * 32 + lane]) * al;
        }
    }
    #pragma unroll
    for (int off = 16; off >= 1; off >>= 1)
        sum += __shfl_xor_sync(0xffffffffu, sum, off);

    float val = acc * (1.f / (sum + 1e-16f)) + b2[lane];
    float m2 = val;
    #pragma unroll
    for (int off = 16; off >= 1; off >>= 1)
        m2 = fmaxf(m2, __shfl_xor_sync(0xffffffffu, m2, off));
    float ex = __expf(val - m2);
    float s2 = ex;
    #pragma unroll
    for (int off = 16; off >= 1; off >>= 1)
        s2 += __shfl_xor_sync(0xffffffffu, s2, off);
    out[(size_t)d * 32 + lane] = val - m2 - logf(s2);
}

// ---------------- launch -----------------------------------------------------
extern "C" void kernel_launch(void* const* d_in, const int* in_sizes, int n_in,
                              void* d_out, int out_size) {
    const float* x    = (const float*)d_in[0];
    const int*   ei   = (const int*)d_in[1];
    const float* W1   = (const float*)d_in[2];
    const float* as1  = (const float*)d_in[3];
    const float* ad1  = (const float*)d_in[4];
    const float* b1   = (const float*)d_in[5];
    const float* W2   = (const float*)d_in[6];
    const float* as2  = (const float*)d_in[7];
    const float* ad2  = (const float*)d_in[8];
    const float* b2   = (const float*)d_in[9];
    float* out = (float*)d_out;

    int n = in_sizes[0] / FIN;
    int E = in_sizes[1] / 2;
    int etot = E + n;

    static cudaStream_t s2 = nullptr;
    static cudaEvent_t evFork = nullptr, evJoin = nullptr;
    if (!s2) {
        cudaStreamCreateWithFlags(&s2, cudaStreamNonBlocking);
        cudaEventCreateWithFlags(&evFork, cudaEventDisableTiming);
        cudaEventCreateWithFlags(&evJoin, cudaEventDisableTiming);
    }

    // fork: CSR build on side stream, overlapped with prep + GEMM1
    cudaEventRecord(evFork, 0);
    cudaStreamWaitEvent(s2, evFork, 0);
    k_deg_init<<<(n + 255) / 256, 256, 0, s2>>>(n);
    k_count<<<(E + 255) / 256, 256, 0, s2>>>(ei, E);
    k_scan<<<1, 1024, 0, s2>>>(n);
    k_scatter<<<(etot + 255) / 256, 256, 0, s2>>>(ei, E, etot);
    cudaEventRecord(evJoin, s2);

    // main stream: dense path
    k_prep_w<<<(256 * 256 + 32 * 256 + 255) / 256, 256>>>(W1, W2);

    dim3 g1(2, (n + 127) / 128);
    k_gemm1_mma<<<g1, 256>>>(x, as1, ad1, n);

    // join: aggregation needs the CSR
    cudaStreamWaitEvent(0, evJoin, 0);

    k_agg1<<<n, 128>>>(b1);

    k_gemm2_mma<<<(n + 127) / 128, 256>>>(as2, ad2, n);
    k_agg2<<<(n * 32 + 255) / 256, 256>>>(b2, out, n);
}

// round 17
// speedup vs baseline: 1.5986x; 1.3579x over previous
#include <cuda_runtime.h>
#include <cuda_bf16.h>
#include <math.h>
#include <stdint.h>

#define NN    50000
#define EE    800000
#define FIN   256
#define ETOT  (EE + NN)
#define NEG_SLOPE 0.2f
#define SCAN_TILE 512
#define NTILES ((NN + SCAN_TILE - 1) / SCAN_TILE)

// ---------------- scratch (device globals) ----------------------------------
__device__ __nv_bfloat16 g_h1[NN * 256];   // layer-1 linear output, bf16 [N,4,64]
__device__ float g_as1[NN * 4];
__device__ float g_ad1[NN * 4];
__device__ float g_h2[NN * 32];            // layer-2 linear output
__device__ float g_as2[NN];
__device__ float g_ad2[NN];
// bf16 operands for tensor-core GEMMs
__device__ __nv_bfloat16 g_w1hi[256 * 256];   // [n][k] (transposed W1), bf16
__device__ __nv_bfloat16 g_a2[NN * 256];      // relu(agg1+b1), bf16
__device__ __nv_bfloat16 g_w2hi[32 * 256];    // [n][k] (transposed W2) split
__device__ __nv_bfloat16 g_w2lo[32 * 256];
// CSR (dst-bucketed incoming edges; slot stores src node id)
__device__ int   g_deg[NN];
__device__ int   g_rowstart[NN + 1];
__device__ int   g_col[ETOT];
__device__ int   g_tilesum[NTILES + 1];

// ---------------- CSR build --------------------------------------------------
__global__ void k_deg_init(int n) {
    int i = blockIdx.x * blockDim.x + threadIdx.x;
    if (i < n) g_deg[i] = 1;
}
__global__ void k_count(const int* __restrict__ ei, int E) {
    int e = blockIdx.x * blockDim.x + threadIdx.x;
    if (e < E) atomicAdd(&g_deg[ei[E + e]], 1);
}
// phase A: per-tile sums (coalesced)
__global__ void k_scanA(int n) {
    __shared__ int sh[256];
    int t = blockIdx.x;
    int tid = threadIdx.x;
    int i0 = t * SCAN_TILE + tid;
    int s = 0;
    if (i0 < n) s += g_deg[i0];
    if (i0 + 256 < n && i0 + 256 < (t + 1) * SCAN_TILE) s += g_deg[i0 + 256];
    sh[tid] = s;
    __syncthreads();
    #pragma unroll
    for (int off = 128; off >= 1; off >>= 1) {
        if (tid < off) sh[tid] += sh[tid + off];
        __syncthreads();
    }
    if (tid == 0) g_tilesum[t] = sh[0];
}
// phase B: single-block exclusive scan of tile sums (+ total -> rowstart[n])
__global__ void k_scanB(int ntiles, int n) {
    __shared__ int sh[NTILES];
    int tid = threadIdx.x;
    if (tid < ntiles) sh[tid] = g_tilesum[tid];
    __syncthreads();
    if (tid == 0) {
        int run = 0;
        for (int i = 0; i < ntiles; i++) {
            int c = sh[i];
            sh[i] = run;
            run += c;
        }
        g_rowstart[n] = run;
    }
    __syncthreads();
    if (tid < ntiles) g_tilesum[tid] = sh[tid];
}
// phase C: per-tile block exclusive scan + writeback (coalesced)
__global__ void k_scanC(int n) {
    __shared__ int sh[SCAN_TILE];
    int t = blockIdx.x;
    int tid = threadIdx.x;
    int base = t * SCAN_TILE;
    #pragma unroll
    for (int k = 0; k < 2; k++) {
        int i = base + tid + k * 256;
        sh[tid + k * 256] = (i < n) ? g_deg[i] : 0;
    }
    __syncthreads();
    // Hillis-Steele inclusive scan over 512
    for (int off = 1; off < SCAN_TILE; off <<= 1) {
        int v0 = (tid >= off) ? sh[tid - off] : 0;
        int i1 = tid + 256;
        int v1 = (i1 >= off) ? sh[i1 - off] : 0;
        __syncthreads();
        sh[tid] += v0;
        sh[i1] += v1;
        __syncthreads();
    }
    int toff = g_tilesum[t];
    #pragma unroll
    for (int k = 0; k < 2; k++) {
        int li = tid + k * 256;
        int i = base + li;
        if (i < n) {
            int excl = toff + (li > 0 ? sh[li - 1] : 0);
            g_rowstart[i] = excl;
            g_deg[i] = excl;          // scatter cursor
        }
    }
}
__global__ void k_scatter(const int* __restrict__ ei, int E, int etot) {
    int e = blockIdx.x * blockDim.x + threadIdx.x;
    if (e >= etot) return;
    int s, d;
    if (e < E) { s = ei[e]; d = ei[E + e]; }
    else       { s = d = e - E; }
    int pos = atomicAdd(&g_deg[d], 1);
    g_col[pos] = s;
}

// ---------------- weight prep: W1 bf16, W2 split bf16 ------------------------
__global__ void k_prep_w(const float* __restrict__ W1, const float* __restrict__ W2) {
    int i = blockIdx.x * blockDim.x + threadIdx.x;
    if (i < 256 * 256) {
        int n = i >> 8, k = i & 255;
        g_w1hi[i] = __float2bfloat16_rn(W1[k * 256 + n]);
    } else if (i < 256 * 256 + 32 * 256) {
        int j = i - 256 * 256;
        int n = j >> 8, k = j & 255;
        float f = W2[k * 32 + n];
        __nv_bfloat16 hi = __float2bfloat16_rn(f);
        g_w2hi[j] = hi;
        g_w2lo[j] = __float2bfloat16_rn(f - __bfloat162float(hi));
    }
}

// ---------------- mma.sync helper -------------------------------------------
#define PAD_K 40
__device__ __forceinline__ void mma16816(float* c, const uint32_t* a, const uint32_t* b) {
    asm volatile(
        "mma.sync.aligned.m16n8k16.row.col.f32.bf16.bf16.f32 "
        "{%0,%1,%2,%3}, {%4,%5,%6,%7}, {%8,%9}, {%0,%1,%2,%3};"
        : "+f"(c[0]), "+f"(c[1]), "+f"(c[2]), "+f"(c[3])
        : "r"(a[0]), "r"(a[1]), "r"(a[2]), "r"(a[3]), "r"(b[0]), "r"(b[1]));
}

// ------- GEMM1 pure bf16 mma.sync + fused attn1 dots ------------------------
__global__ void __launch_bounds__(256) k_gemm1_mma(const float* __restrict__ x,
                                                   const float* __restrict__ att_src,
                                                   const float* __restrict__ att_dst, int M) {
    __shared__ __nv_bfloat16 sA[128 * PAD_K];
    __shared__ __nv_bfloat16 sB[128 * PAD_K];

    int tid = threadIdx.x;
    int wid = tid >> 5, lane = tid & 31;
    int wm = wid >> 1, wn = wid & 1;
    int row0 = blockIdx.y * 128;
    int col0 = blockIdx.x * 128;

    float acc[2][8][4] = {};
    int lq = lane & 3;
    int lr = lane >> 2;

    for (int kc = 0; kc < 256; kc += 32) {
        #pragma unroll
        for (int i = 0; i < 2; i++) {
            int slot = tid + i * 256;
            int r = slot >> 2, q = slot & 3;
            int gr = row0 + r;
            __nv_bfloat16 hbuf[8];
            if (gr < M) {
                const float* px = x + (size_t)gr * 256 + kc + q * 8;
                float4 f0 = *(const float4*)px;
                float4 f1 = *(const float4*)(px + 4);
                hbuf[0] = __float2bfloat16_rn(f0.x);
                hbuf[1] = __float2bfloat16_rn(f0.y);
                hbuf[2] = __float2bfloat16_rn(f0.z);
                hbuf[3] = __float2bfloat16_rn(f0.w);
                hbuf[4] = __float2bfloat16_rn(f1.x);
                hbuf[5] = __float2bfloat16_rn(f1.y);
                hbuf[6] = __float2bfloat16_rn(f1.z);
                hbuf[7] = __float2bfloat16_rn(f1.w);
            } else {
                #pragma unroll
                for (int t = 0; t < 8; t++) hbuf[t] = __float2bfloat16_rn(0.f);
            }
            *(uint4*)(sA + r * PAD_K + q * 8) = *(uint4*)hbuf;
        }
        #pragma unroll
        for (int i = 0; i < 2; i++) {
            int slot = tid + i * 256;
            int r = slot >> 2, q = slot & 3;
            int gn = col0 + r;
            *(uint4*)(sB + r * PAD_K + q * 8) = *(const uint4*)(g_w1hi + (size_t)gn * 256 + kc + q * 8);
        }
        __syncthreads();

        #pragma unroll
        for (int ks = 0; ks < 2; ks++) {
            int kb = ks * 16;
            uint32_t a[2][4], b[8][2];
            #pragma unroll
            for (int mt = 0; mt < 2; mt++) {
                int rbase = wm * 32 + mt * 16;
                const __nv_bfloat16* p0 = sA + (rbase + lr) * PAD_K + kb + lq * 2;
                const __nv_bfloat16* p1 = sA + (rbase + 8 + lr) * PAD_K + kb + lq * 2;
                a[mt][0] = *(const uint32_t*)p0;
                a[mt][1] = *(const uint32_t*)p1;
                a[mt][2] = *(const uint32_t*)(p0 + 8);
                a[mt][3] = *(const uint32_t*)(p1 + 8);
            }
            #pragma unroll
            for (int nt = 0; nt < 8; nt++) {
                int nbase = wn * 64 + nt * 8;
                const __nv_bfloat16* p = sB + (nbase + lr) * PAD_K + kb + lq * 2;
                b[nt][0] = *(const uint32_t*)p;
                b[nt][1] = *(const uint32_t*)(p + 8);
            }
            #pragma unroll
            for (int mt = 0; mt < 2; mt++)
                #pragma unroll
                for (int nt = 0; nt < 8; nt++)
                    mma16816(acc[mt][nt], a[mt], b[nt]);
        }
        __syncthreads();
    }

    int h = (col0 >> 6) + wn;
    #pragma unroll
    for (int mt = 0; mt < 2; mt++) {
        int r0 = row0 + wm * 32 + mt * 16 + lr;
        float ps0 = 0.f, pd0 = 0.f, ps1 = 0.f, pd1 = 0.f;
        #pragma unroll
        for (int nt = 0; nt < 8; nt++) {
            int c = col0 + wn * 64 + nt * 8 + lq * 2;
            int ci = h * 64 + nt * 8 + lq * 2;
            float a0 = __ldg(&att_src[ci]), a1 = __ldg(&att_src[ci + 1]);
            float d0 = __ldg(&att_dst[ci]), d1 = __ldg(&att_dst[ci + 1]);
            ps0 += acc[mt][nt][0] * a0 + acc[mt][nt][1] * a1;
            pd0 += acc[mt][nt][0] * d0 + acc[mt][nt][1] * d1;
            ps1 += acc[mt][nt][2] * a0 + acc[mt][nt][3] * a1;
            pd1 += acc[mt][nt][2] * d0 + acc[mt][nt][3] * d1;
            if (r0 < M)
                *(__nv_bfloat162*)(g_h1 + (size_t)r0 * 256 + c) =
                    __float22bfloat162_rn(make_float2(acc[mt][nt][0], acc[mt][nt][1]));
            if (r0 + 8 < M)
                *(__nv_bfloat162*)(g_h1 + (size_t)(r0 + 8) * 256 + c) =
                    __float22bfloat162_rn(make_float2(acc[mt][nt][2], acc[mt][nt][3]));
        }
        #pragma unroll
        for (int off = 1; off <= 2; off <<= 1) {
            ps0 += __shfl_xor_sync(0xffffffffu, ps0, off);
            pd0 += __shfl_xor_sync(0xffffffffu, pd0, off);
            ps1 += __shfl_xor_sync(0xffffffffu, ps1, off);
            pd1 += __shfl_xor_sync(0xffffffffu, pd1, off);
        }
        if (lq == 0) {
            if (r0 < M)     { g_as1[r0 * 4 + h] = ps0;       g_ad1[r0 * 4 + h] = pd0; }
            if (r0 + 8 < M) { g_as1[(r0 + 8) * 4 + h] = ps1; g_ad1[(r0 + 8) * 4 + h] = pd1; }
        }
    }
}

// -- fused layer-1 softmax + aggregate + bias + relu -> bf16 ------------------
// warp per dst (4 dsts/block, sync-free). Lane owns 8 channels (uint4 gather);
// alphas computed lane-parallel as float4 (all heads), broadcast via 4 shfls.
__global__ void __launch_bounds__(128) k_agg1(const float* __restrict__ b1, int n) {
    int d = blockIdx.x * 4 + (threadIdx.x >> 5);
    int lane = threadIdx.x & 31;
    if (d >= n) return;
    int beg = g_rowstart[d], end = g_rowstart[d + 1];
    float4 adv = *(const float4*)&g_ad1[d * 4];
    int h = lane >> 3;                  // head of this lane's 8 channels

    // phase A: lane-parallel max (all 4 heads)
    float4 mx = make_float4(-3.4e38f, -3.4e38f, -3.4e38f, -3.4e38f);
    for (int i = beg + lane; i < end; i += 32) {
        float4 a = __ldg((const float4*)&g_as1[__ldg(&g_col[i]) * 4]);
        float vx = a.x + adv.x, vy = a.y + adv.y, vz = a.z + adv.z, vw = a.w + adv.w;
        vx = (vx > 0.f) ? vx : NEG_SLOPE * vx;
        vy = (vy > 0.f) ? vy : NEG_SLOPE * vy;
        vz = (vz > 0.f) ? vz : NEG_SLOPE * vz;
        vw = (vw > 0.f) ? vw : NEG_SLOPE * vw;
        mx.x = fmaxf(mx.x, vx); mx.y = fmaxf(mx.y, vy);
        mx.z = fmaxf(mx.z, vz); mx.w = fmaxf(mx.w, vw);
    }
    #pragma unroll
    for (int off = 16; off >= 1; off >>= 1) {
        mx.x = fmaxf(mx.x, __shfl_xor_sync(0xffffffffu, mx.x, off));
        mx.y = fmaxf(mx.y, __shfl_xor_sync(0xffffffffu, mx.y, off));
        mx.z = fmaxf(mx.z, __shfl_xor_sync(0xffffffffu, mx.z, off));
        mx.w = fmaxf(mx.w, __shfl_xor_sync(0xffffffffu, mx.w, off));
    }

    // phase B: 32-edge chunks; per-lane alphas, shfl broadcast, uint4 gather
    float4 sum = make_float4(0.f, 0.f, 0.f, 0.f);
    float acc[8] = {};
    for (int base = beg; base < end; base += 32) {
        int i = base + lane;
        float4 al = make_float4(0.f, 0.f, 0.f, 0.f);
        int mycol = 0;
        if (i < end) {
            mycol = __ldg(&g_col[i]);
            float4 a = __ldg((const float4*)&g_as1[mycol * 4]);
            float vx = a.x + adv.x, vy = a.y + adv.y, vz = a.z + adv.z, vw = a.w + adv.w;
            vx = (vx > 0.f) ? vx : NEG_SLOPE * vx;
            vy = (vy > 0.f) ? vy : NEG_SLOPE * vy;
            vz = (vz > 0.f) ? vz : NEG_SLOPE * vz;
            vw = (vw > 0.f) ? vw : NEG_SLOPE * vw;
            al = make_float4(__expf(vx - mx.x), __expf(vy - mx.y),
                             __expf(vz - mx.z), __expf(vw - mx.w));
        }
        sum.x += al.x; sum.y += al.y; sum.z += al.z; sum.w += al.w;
        int cnt = min(32, end - base);
        for (int j = 0; j < cnt; j++) {
            int s   = __shfl_sync(0xffffffffu, mycol, j);
            float a0 = __shfl_sync(0xffffffffu, al.x, j);
            float a1 = __shfl_sync(0xffffffffu, al.y, j);
            float a2 = __shfl_sync(0xffffffffu, al.z, j);
            float a3 = __shfl_sync(0xffffffffu, al.w, j);
            float w = (h == 0) ? a0 : (h == 1) ? a1 : (h == 2) ? a2 : a3;
            uint4 raw = __ldg((const uint4*)(g_h1 + (size_t)s * 256 + lane * 8));
            const __nv_bfloat162* bp = (const __nv_bfloat162*)&raw;
            #pragma unroll
            for (int k = 0; k < 4; k++) {
                float2 v = __bfloat1622float2(bp[k]);
                acc[k * 2 + 0] += v.x * w;
                acc[k * 2 + 1] += v.y * w;
            }
        }
    }
    #pragma unroll
    for (int off = 16; off >= 1; off >>= 1) {
        sum.x += __shfl_xor_sync(0xffffffffu, sum.x, off);
        sum.y += __shfl_xor_sync(0xffffffffu, sum.y, off);
        sum.z += __shfl_xor_sync(0xffffffffu, sum.z, off);
        sum.w += __shfl_xor_sync(0xffffffffu, sum.w, off);
    }
    float sh = (h == 0) ? sum.x : (h == 1) ? sum.y : (h == 2) ? sum.z : sum.w;
    float rs = 1.f / (sh + 1e-16f);

    __nv_bfloat162 outp[4];
    #pragma unroll
    for (int k = 0; k < 4; k++) {
        float v0 = fmaxf(acc[k * 2 + 0] * rs + __ldg(&b1[lane * 8 + k * 2 + 0]), 0.f);
        float v1 = fmaxf(acc[k * 2 + 1] * rs + __ldg(&b1[lane * 8 + k * 2 + 1]), 0.f);
        outp[k] = __float22bfloat162_rn(make_float2(v0, v1));
    }
    *(uint4*)(g_a2 + (size_t)d * 256 + lane * 8) = *(uint4*)outp;
}

// ------- GEMM2: a2(bf16) x W2(split), 2 products + fused attn2 dots ---------
__global__ void __launch_bounds__(256) k_gemm2_mma(const float* __restrict__ att_src,
                                                   const float* __restrict__ att_dst, int M) {
    __shared__ __nv_bfloat16 sA[128 * PAD_K];
    __shared__ __nv_bfloat16 sBhi[32 * PAD_K];
    __shared__ __nv_bfloat16 sBlo[32 * PAD_K];

    int tid = threadIdx.x;
    int wid = tid >> 5, lane = tid & 31;
    int row0 = blockIdx.x * 128;
    int lq = lane & 3;
    int lr = lane >> 2;

    float acc[4][4] = {};

    for (int kc = 0; kc < 256; kc += 32) {
        #pragma unroll
        for (int i = 0; i < 2; i++) {
            int slot = tid + i * 256;
            int r = slot >> 2, q = slot & 3;
            int gr = row0 + r;
            uint4 v = make_uint4(0, 0, 0, 0);
            if (gr < M) v = *(const uint4*)(g_a2 + (size_t)gr * 256 + kc + q * 8);
            *(uint4*)(sA + r * PAD_K + q * 8) = v;
        }
        if (tid < 128) {
            int r = tid >> 2, q = tid & 3;
            *(uint4*)(sBhi + r * PAD_K + q * 8) = *(const uint4*)(g_w2hi + (size_t)r * 256 + kc + q * 8);
            *(uint4*)(sBlo + r * PAD_K + q * 8) = *(const uint4*)(g_w2lo + (size_t)r * 256 + kc + q * 8);
        }
        __syncthreads();

        #pragma unroll
        for (int ks = 0; ks < 2; ks++) {
            int kb = ks * 16;
            uint32_t a[4], bhi[4][2], blo[4][2];
            int rbase = wid * 16;
            const __nv_bfloat16* p0 = sA + (rbase + lr) * PAD_K + kb + lq * 2;
            const __nv_bfloat16* p1 = sA + (rbase + 8 + lr) * PAD_K + kb + lq * 2;
            a[0] = *(const uint32_t*)p0;
            a[1] = *(const uint32_t*)p1;
            a[2] = *(const uint32_t*)(p0 + 8);
            a[3] = *(const uint32_t*)(p1 + 8);
            #pragma unroll
            for (int nt = 0; nt < 4; nt++) {
                int nbase = nt * 8;
                const __nv_bfloat16* ph = sBhi + (nbase + lr) * PAD_K + kb + lq * 2;
                const __nv_bfloat16* pl = sBlo + (nbase + lr) * PAD_K + kb + lq * 2;
                bhi[nt][0] = *(const uint32_t*)ph;
                bhi[nt][1] = *(const uint32_t*)(ph + 8);
                blo[nt][0] = *(const uint32_t*)pl;
                blo[nt][1] = *(const uint32_t*)(pl + 8);
            }
            #pragma unroll
            for (int nt = 0; nt < 4; nt++) {
                mma16816(acc[nt], a, bhi[nt]);
                mma16816(acc[nt], a, blo[nt]);
            }
        }
        __syncthreads();
    }

    int r0 = row0 + wid * 16 + lr;
    float ps0 = 0.f, pd0 = 0.f, ps1 = 0.f, pd1 = 0.f;
    #pragma unroll
    for (int nt = 0; nt < 4; nt++) {
        int c = nt * 8 + lq * 2;
        float a0 = __ldg(&att_src[c]), a1 = __ldg(&att_src[c + 1]);
        float d0 = __ldg(&att_dst[c]), d1 = __ldg(&att_dst[c + 1]);
        ps0 += acc[nt][0] * a0 + acc[nt][1] * a1;
        pd0 += acc[nt][0] * d0 + acc[nt][1] * d1;
        ps1 += acc[nt][2] * a0 + acc[nt][3] * a1;
        pd1 += acc[nt][2] * d0 + acc[nt][3] * d1;
        if (r0 < M)
            *(float2*)(g_h2 + (size_t)r0 * 32 + c) = make_float2(acc[nt][0], acc[nt][1]);
        if (r0 + 8 < M)
            *(float2*)(g_h2 + (size_t)(r0 + 8) * 32 + c) = make_float2(acc[nt][2], acc[nt][3]);
    }
    #pragma unroll
    for (int off = 1; off <= 2; off <<= 1) {
        ps0 += __shfl_xor_sync(0xffffffffu, ps0, off);
        pd0 += __shfl_xor_sync(0xffffffffu, pd0, off);
        ps1 += __shfl_xor_sync(0xffffffffu, ps1, off);
        pd1 += __shfl_xor_sync(0xffffffffu, pd1, off);
    }
    if (lq == 0) {
        if (r0 < M)     { g_as2[r0] = ps0;     g_ad2[r0] = pd0; }
        if (r0 + 8 < M) { g_as2[r0 + 8] = ps1; g_ad2[r0 + 8] = pd1; }
    }
}

// -- fused layer-2 softmax+aggregate+bias+log_softmax (warp/dst, lane-par) ---
__global__ void __launch_bounds__(256) k_agg2(const float* __restrict__ b2,
                                              float* __restrict__ out, int n) {
    int d = (blockIdx.x * blockDim.x + threadIdx.x) >> 5;
    int lane = threadIdx.x & 31;
    if (d >= n) return;
    int beg = g_rowstart[d], end = g_rowstart[d + 1];
    float adv = __ldg(&g_ad2[d]);

    float mx = -3.4e38f;
    for (int i = beg + lane; i < end; i += 32) {
        float v = __ldg(&g_as2[__ldg(&g_col[i])]) + adv;
        v = (v > 0.f) ? v : NEG_SLOPE * v;
        mx = fmaxf(mx, v);
    }
    #pragma unroll
    for (int off = 16; off >= 1; off >>= 1)
        mx = fmaxf(mx, __shfl_xor_sync(0xffffffffu, mx, off));

    float sum = 0.f, acc = 0.f;
    for (int base = beg; base < end; base += 32) {
        int i = base + lane;
        float myal = 0.f; int mycol = 0;
        if (i < end) {
            mycol = __ldg(&g_col[i]);
            float v = __ldg(&g_as2[mycol]) + adv;
            v = (v > 0.f) ? v : NEG_SLOPE * v;
            myal = __expf(v - mx);
        }
        sum += myal;
        int cnt = min(32, end - base);
        for (int j = 0; j < cnt; j++) {
            float al = __shfl_sync(0xffffffffu, myal, j);
            int s    = __shfl_sync(0xffffffffu, mycol, j);
            acc += __ldg(&g_h2[(size_t)s * 32 + lane]) * al;
        }
    }
    #pragma unroll
    for (int off = 16; off >= 1; off >>= 1)
        sum += __shfl_xor_sync(0xffffffffu, sum, off);

    float val = acc * (1.f / (sum + 1e-16f)) + b2[lane];
    float m2 = val;
    #pragma unroll
    for (int off = 16; off >= 1; off >>= 1)
        m2 = fmaxf(m2, __shfl_xor_sync(0xffffffffu, m2, off));
    float ex = __expf(val - m2);
    float s2 = ex;
    #pragma unroll
    for (int off = 16; off >= 1; off >>= 1)
        s2 += __shfl_xor_sync(0xffffffffu, s2, off);
    out[(size_t)d * 32 + lane] = val - m2 - logf(s2);
}

// ---------------- launch -----------------------------------------------------
extern "C" void kernel_launch(void* const* d_in, const int* in_sizes, int n_in,
                              void* d_out, int out_size) {
    const float* x    = (const float*)d_in[0];
    const int*   ei   = (const int*)d_in[1];
    const float* W1   = (const float*)d_in[2];
    const float* as1  = (const float*)d_in[3];
    const float* ad1  = (const float*)d_in[4];
    const float* b1   = (const float*)d_in[5];
    const float* W2   = (const float*)d_in[6];
    const float* as2  = (const float*)d_in[7];
    const float* ad2  = (const float*)d_in[8];
    const float* b2   = (const float*)d_in[9];
    float* out = (float*)d_out;

    int n = in_sizes[0] / FIN;
    int E = in_sizes[1] / 2;
    int etot = E + n;
    int ntiles = (n + SCAN_TILE - 1) / SCAN_TILE;

    static cudaStream_t s2 = nullptr;
    static cudaEvent_t evFork = nullptr, evJoin = nullptr;
    if (!s2) {
        cudaStreamCreateWithFlags(&s2, cudaStreamNonBlocking);
        cudaEventCreateWithFlags(&evFork, cudaEventDisableTiming);
        cudaEventCreateWithFlags(&evJoin, cudaEventDisableTiming);
    }

    // fork: CSR build on side stream, overlapped with prep + GEMM1
    cudaEventRecord(evFork, 0);
    cudaStreamWaitEvent(s2, evFork, 0);
    k_deg_init<<<(n + 255) / 256, 256, 0, s2>>>(n);
    k_count<<<(E + 255) / 256, 256, 0, s2>>>(ei, E);
    k_scanA<<<ntiles, 256, 0, s2>>>(n);
    k_scanB<<<1, ((ntiles + 31) / 32) * 32, 0, s2>>>(ntiles, n);
    k_scanC<<<ntiles, 256, 0, s2>>>(n);
    k_scatter<<<(etot + 255) / 256, 256, 0, s2>>>(ei, E, etot);
    cudaEventRecord(evJoin, s2);

    // main stream: dense path
    k_prep_w<<<(256 * 256 + 32 * 256 + 255) / 256, 256>>>(W1, W2);

    dim3 g1(2, (n + 127) / 128);
    k_gemm1_mma<<<g1, 256>>>(x, as1, ad1, n);

    // join: aggregation needs the CSR
    cudaStreamWaitEvent(0, evJoin, 0);

    k_agg1<<<(n + 3) / 4, 128>>>(b1, n);

    k_gemm2_mma<<<(n + 127) / 128, 256>>>(as2, ad2, n);
    k_agg2<<<(n * 32 + 255) / 256, 256>>>(b2, out, n);
}